// round 13
// baseline (speedup 1.0000x reference)
#include <cuda_runtime.h>
#include <math.h>

typedef unsigned long long ull;

// ---- problem constants ----
#define BB  16
#define HH  384
#define WW  512
#define HPP 191
#define WPP 255
#define H2D 189
#define W2D 253
#define H3D 187
#define W3D 251
#define NPIX (H3D*W3D)   // 46937
#define NEGV (-1e30f)
#define THRESH_V 0.6f
#define KPICKS 128
#define CAP 5600
#define SP  260          // padded row stride (mult of 4)
#define PH  196          // padded plane height

// staging layout offsets (in ull) — ALL EVEN for aligned ulonglong2 loads
#define W1OFF 0
#define W1N   135
#define W2OFF 136
#define W2N   720
#define W3OFF 856
#define W3N   2304
#define WTOT  3160

// ---- scratch (zero-initialized device globals; padding deterministic) ----
__device__ __align__(16) float  g_pool[BB*10*PH*SP];
__device__ __align__(16) float  g_h2[BB*16*PH*SP];
__device__ __align__(16) ull    g_stage[WTOT];
__device__ int    g_cnt[BB];
__device__ int    g_cand[BB*NPIX];      // packed (y<<16)|x
__device__ float  g_cand_sc[BB*NPIX];
__device__ int    g_pick[BB*KPICKS];    // packed (y<<16)|x of NMS picks
__device__ float  g_pick_sc[BB*KPICKS];
__device__ int    g_pcnt[BB];

// ---- packed oc-pair weights in constant memory (reuse 4x -> port OK) ----
__constant__ ull c_w1[W1N];    // [(c*9+k)*5  + q]
__constant__ ull c_w2[W2N];    // [(c*9+k)*8  + q]
__constant__ ull c_w3[W3N];    // [(c*9+k)*16 + q]

// ---- f32x2 helpers ----
__device__ __forceinline__ ull pack2(float lo, float hi){
    ull r; asm("mov.b64 %0, {%1, %2};" : "=l"(r) : "f"(lo), "f"(hi)); return r;
}
__device__ __forceinline__ void unpack2(ull v, float &lo, float &hi){
    asm("mov.b64 {%0, %1}, %2;" : "=f"(lo), "=f"(hi) : "l"(v));
}
__device__ __forceinline__ void fma2(ull &d, ull a, ull b){
    asm("fma.rn.f32x2 %0, %1, %2, %0;" : "+l"(d) : "l"(a), "l"(b));
}

// ============================================================
// K0: pack weights into oc-pair layout + zero counters
// ============================================================
__global__ void k0_pack(const float* __restrict__ w1,
                        const float* __restrict__ w2,
                        const float* __restrict__ w3)
{
    int tid = threadIdx.x;
    if (tid < BB) g_cnt[tid] = 0;
    for (int i = tid; i < W1N; i += 256){
        int ck = i / 5, q = i % 5;
        g_stage[W1OFF + i] = pack2(w1[(2*q)*27 + ck], w1[(2*q+1)*27 + ck]);
    }
    for (int i = tid; i < W2N; i += 256){
        int ck = i >> 3, q = i & 7;
        g_stage[W2OFF + i] = pack2(w2[(2*q)*90 + ck], w2[(2*q+1)*90 + ck]);
    }
    for (int i = tid; i < W3N; i += 256){
        int ck = i >> 4, q = i & 15;
        g_stage[W3OFF + i] = pack2(w3[(2*q)*144 + ck], w3[(2*q+1)*144 + ck]);
    }
}

// ============================================================
// K1: normalize + conv1(3x3,3->10) + PReLU + maxpool2x2  [R5]
// ============================================================
__global__ __launch_bounds__(256) void k1_conv1_pool(const float* __restrict__ im,
                              const float* __restrict__ b,
                              const float* __restrict__ p)
{
    __shared__ float sb[10], sp[10];
    int tid = threadIdx.y * 32 + threadIdx.x;
    if (tid < 10){ sb[tid] = b[tid]; sp[tid] = p[tid]; }
    __syncthreads();

    int ox = blockIdx.x * 32 + threadIdx.x;
    int oy = blockIdx.y * 8  + threadIdx.y;
    int bb = blockIdx.z;
    if (ox >= WPP || oy >= HPP) return;

    ull acc[4][5];
#pragma unroll
    for (int q = 0; q < 5; q++){
        ull bi = pack2(sb[2*q], sb[2*q+1]);
        acc[0][q] = bi; acc[1][q] = bi; acc[2][q] = bi; acc[3][q] = bi;
    }

#pragma unroll
    for (int c = 0; c < 3; c++){
        const float* base = im + ((bb*3 + c)*HH + 2*oy)*WW + 2*ox;
        ull du[4][4];
#pragma unroll
        for (int r = 0; r < 4; r++){
            float2 u01 = *reinterpret_cast<const float2*>(base + r*WW);
            float2 u23 = *reinterpret_cast<const float2*>(base + r*WW + 2);
            float v0 = (u01.x - 127.5f)*0.0078125f;
            float v1 = (u01.y - 127.5f)*0.0078125f;
            float v2 = (u23.x - 127.5f)*0.0078125f;
            float v3 = (u23.y - 127.5f)*0.0078125f;
            du[r][0] = pack2(v0,v0); du[r][1] = pack2(v1,v1);
            du[r][2] = pack2(v2,v2); du[r][3] = pack2(v3,v3);
        }
#pragma unroll
        for (int ky = 0; ky < 3; ky++)
#pragma unroll
        for (int kx = 0; kx < 3; kx++){
            const ull* wq = &c_w1[(c*9 + ky*3 + kx)*5];
#pragma unroll
            for (int q = 0; q < 5; q++){
                ull wv = wq[q];
                fma2(acc[0][q], du[ky  ][kx  ], wv);
                fma2(acc[1][q], du[ky  ][kx+1], wv);
                fma2(acc[2][q], du[ky+1][kx  ], wv);
                fma2(acc[3][q], du[ky+1][kx+1], wv);
            }
        }
    }
#pragma unroll
    for (int q = 0; q < 5; q++){
        float h[4][2];
#pragma unroll
        for (int pp = 0; pp < 4; pp++) unpack2(acc[pp][q], h[pp][0], h[pp][1]);
#pragma unroll
        for (int s = 0; s < 2; s++){
            int oc = 2*q + s;
            float al = sp[oc];
            float m = -INFINITY;
#pragma unroll
            for (int pp = 0; pp < 4; pp++){
                float v = h[pp][s];
                v = v > 0.f ? v : al*v;
                m = fmaxf(m, v);
            }
            g_pool[((bb*10 + oc)*PH + oy)*SP + ox] = m;
        }
    }
}

// ============================================================
// K2: conv2(3x3,10->16) + PReLU, 4 px/thread  [R5 engine]
// block (32,2)=64 thr -> ~6 blocks/SM: finer waves, 12 warps
// ============================================================
__global__ __launch_bounds__(64) void k2_conv2(const float* __restrict__ b,
                         const float* __restrict__ p)
{
    __shared__ float sb[16], sp[16];
    int tid = threadIdx.y * 32 + threadIdx.x;
    if (tid < 16){ sb[tid] = b[tid]; sp[tid] = p[tid]; }
    __syncthreads();

    int x0 = blockIdx.x * 128 + threadIdx.x * 4;  // <= 252; reads <= 257 < SP
    int oy = blockIdx.y * 2   + threadIdx.y;      // <= 191; reads rows <= 193 < PH
    int bb = blockIdx.z;

    ull acc[4][8];
#pragma unroll
    for (int q = 0; q < 8; q++){
        ull bi = pack2(sb[2*q], sb[2*q+1]);
        acc[0][q] = bi; acc[1][q] = bi; acc[2][q] = bi; acc[3][q] = bi;
    }

    for (int c = 0; c < 10; c++){
        const float* base = g_pool + ((bb*10 + c)*PH + oy)*SP + x0;
        ull du[3][6];
#pragma unroll
        for (int r = 0; r < 3; r++){
            float4 a4 = *reinterpret_cast<const float4*>(base + r*SP);
            float2 b2 = *reinterpret_cast<const float2*>(base + r*SP + 4);
            du[r][0] = pack2(a4.x,a4.x); du[r][1] = pack2(a4.y,a4.y);
            du[r][2] = pack2(a4.z,a4.z); du[r][3] = pack2(a4.w,a4.w);
            du[r][4] = pack2(b2.x,b2.x); du[r][5] = pack2(b2.y,b2.y);
        }
#pragma unroll
        for (int ky = 0; ky < 3; ky++)
#pragma unroll
        for (int kx = 0; kx < 3; kx++){
            const ull* wq = &c_w2[(c*9 + ky*3 + kx)*8];
#pragma unroll
            for (int q = 0; q < 8; q++){
                ull wv = wq[q];
#pragma unroll
                for (int pp = 0; pp < 4; pp++)
                    fma2(acc[pp][q], du[ky][kx+pp], wv);
            }
        }
    }
#pragma unroll
    for (int q = 0; q < 8; q++){
        float v[4][2];
#pragma unroll
        for (int pp = 0; pp < 4; pp++) unpack2(acc[pp][q], v[pp][0], v[pp][1]);
#pragma unroll
        for (int s = 0; s < 2; s++){
            int oc = 2*q + s;
            float al = sp[oc];
            float4 o;
            float t0 = v[0][s]; o.x = t0 > 0.f ? t0 : al*t0;
            float t1 = v[1][s]; o.y = t1 > 0.f ? t1 : al*t1;
            float t2 = v[2][s]; o.z = t2 > 0.f ? t2 : al*t2;
            float t3 = v[3][s]; o.w = t3 > 0.f ? t3 : al*t3;
            *reinterpret_cast<float4*>(&g_h2[((bb*16 + oc)*PH + oy)*SP + x0]) = o;
        }
    }
}

// ============================================================
// K3: conv3(3x3,16->32)+PReLU + score head ONLY + append.
// R5 engine, 4 px/thread; block (32,2)=64 thr.
// ============================================================
__global__ __launch_bounds__(64) void k3_conv3_heads(const float* __restrict__ b3,
                               const float* __restrict__ p3,
                               const float* __restrict__ w41, const float* __restrict__ b41)
{
    __shared__ float sb[32], sp[32];
    __shared__ float sw41[64], sb41[2];
    int tid = threadIdx.y * 32 + threadIdx.x;
    if (tid < 32){ sb[tid] = b3[tid]; sp[tid] = p3[tid]; }
    if (tid < 64)  sw41[tid] = w41[tid];
    if (tid < 2)   sb41[tid] = b41[tid];
    __syncthreads();

    int x0 = blockIdx.x * 128 + threadIdx.x * 4;  // <= 252; reads <= 257 < SP
    int oy = blockIdx.y * 2   + threadIdx.y;      // <= 187; reads rows <= 189 < PH
    int bb = blockIdx.z;

    ull acc[4][16];
#pragma unroll
    for (int q = 0; q < 16; q++){
        ull bi = pack2(sb[2*q], sb[2*q+1]);
        acc[0][q] = bi; acc[1][q] = bi; acc[2][q] = bi; acc[3][q] = bi;
    }

    for (int c = 0; c < 16; c++){
        const float* base = g_h2 + ((bb*16 + c)*PH + oy)*SP + x0;
        ull du[3][6];
#pragma unroll
        for (int r = 0; r < 3; r++){
            float4 a4 = *reinterpret_cast<const float4*>(base + r*SP);
            float2 b2 = *reinterpret_cast<const float2*>(base + r*SP + 4);
            du[r][0] = pack2(a4.x,a4.x); du[r][1] = pack2(a4.y,a4.y);
            du[r][2] = pack2(a4.z,a4.z); du[r][3] = pack2(a4.w,a4.w);
            du[r][4] = pack2(b2.x,b2.x); du[r][5] = pack2(b2.y,b2.y);
        }
#pragma unroll
        for (int ky = 0; ky < 3; ky++)
#pragma unroll
        for (int kx = 0; kx < 3; kx++){
            const ull* wq = &c_w3[(c*9 + ky*3 + kx)*16];
#pragma unroll
            for (int q = 0; q < 16; q++){
                ull wv = wq[q];
#pragma unroll
                for (int pp = 0; pp < 4; pp++)
                    fma2(acc[pp][q], du[ky][kx+pp], wv);
            }
        }
    }

    // score head only (l chains identical to R5's — r-FMAs removed)
    float l0[4], l1[4];
#pragma unroll
    for (int pp = 0; pp < 4; pp++){ l0[pp] = sb41[0]; l1[pp] = sb41[1]; }
#pragma unroll
    for (int q = 0; q < 16; q++){
        float wA0 = sw41[2*q],    wA1 = sw41[2*q+1];
        float wB0 = sw41[32+2*q], wB1 = sw41[32+2*q+1];
        float alo = sp[2*q], ahi = sp[2*q+1];
#pragma unroll
        for (int pp = 0; pp < 4; pp++){
            float hA, hB; unpack2(acc[pp][q], hA, hB);
            hA = hA > 0.f ? hA : alo*hA;
            hB = hB > 0.f ? hB : ahi*hB;
            l0[pp] = fmaf(hA, wA0, fmaf(hB, wA1, l0[pp]));
            l1[pp] = fmaf(hA, wB0, fmaf(hB, wB1, l1[pp]));
        }
    }
    if (oy < H3D){
#pragma unroll
        for (int pp = 0; pp < 4; pp++){
            int x = x0 + pp;
            if (x >= W3D) continue;
            float prob = 1.f / (1.f + expf(l0[pp] - l1[pp]));
            if (prob >= THRESH_V){
                int pos = atomicAdd(&g_cnt[bb], 1);
                if (pos < NPIX){
                    g_cand[bb*NPIX + pos]    = (oy << 16) | x;
                    g_cand_sc[bb*NPIX + pos] = prob;
                }
            }
        }
    }
}

// ============================================================
// K4: per-batch iterative argmax NMS. Records picks (xy, score);
// box refinement deferred to k5 (suppression is pure geometry).
// Tie-break (score desc, packed xy asc) == pixel-index order.
// IoU>0.5 for 12x12 stride-2 boxes  <=>  |dx|<=1 && |dy|<=1.
// ============================================================
__global__ void k4_nms(float* __restrict__ out)
{
    const int NT = 256;
    int bb = blockIdx.x, tid = threadIdx.x;
    int lane = tid & 31, wrp = tid >> 5;

    __shared__ float s_sc[CAP];
    __shared__ int   s_xy[CAP];
    __shared__ float w_s[8];
    __shared__ int   w_xy[8], w_i[8];
    __shared__ float sh_best;
    __shared__ int   sh_j, sh_xy;

    if (tid == 0) g_pcnt[bb] = KPICKS;

    int count = g_cnt[bb];
    if (count > NPIX) count = NPIX;
    bool insh = (count <= CAP);
    float* scp;
    const int* xyp;
    if (insh){
        for (int i = tid; i < count; i += NT){
            s_sc[i] = g_cand_sc[bb*NPIX + i];
            s_xy[i] = g_cand[bb*NPIX + i];
        }
        scp = s_sc; xyp = s_xy;
    } else {
        scp = g_cand_sc + bb*NPIX;
        xyp = g_cand + bb*NPIX;
    }
    __syncthreads();

    for (int k = 0; k < KPICKS; k++){
        float bs = -INFINITY; int bxy = 0x7fffffff; int bi = -1;
        for (int i = tid; i < count; i += NT){
            float v = scp[i]; int xy = xyp[i];
            if (v > bs || (v == bs && xy < bxy)){ bs = v; bxy = xy; bi = i; }
        }
#pragma unroll
        for (int off = 16; off > 0; off >>= 1){
            float vs  = __shfl_down_sync(0xffffffffu, bs,  off);
            int   vxy = __shfl_down_sync(0xffffffffu, bxy, off);
            int   vi  = __shfl_down_sync(0xffffffffu, bi,  off);
            if (vs > bs || (vs == bs && vxy < bxy)){ bs = vs; bxy = vxy; bi = vi; }
        }
        if (lane == 0){ w_s[wrp] = bs; w_xy[wrp] = bxy; w_i[wrp] = bi; }
        __syncthreads();
        if (tid == 0){
            float cs = w_s[0]; int cxy = w_xy[0], ci = w_i[0];
#pragma unroll
            for (int t = 1; t < 8; t++){
                if (w_s[t] > cs || (w_s[t] == cs && w_xy[t] < cxy)){
                    cs = w_s[t]; cxy = w_xy[t]; ci = w_i[t];
                }
            }
            sh_best = cs; sh_j = ci; sh_xy = cxy;
        }
        __syncthreads();
        float best = sh_best; int j = sh_j; int jxy = sh_xy;

        if (!(best > -0.5e30f) || j < 0){
            if (tid == 0) g_pcnt[bb] = k;
            // exhausted: remaining picks have ok=false -> zero rows
            int n0 = (KPICKS - k) * 5;
            float* o0 = out + ((size_t)bb*KPICKS + k)*5;
            for (int t = tid; t < n0; t += NT) o0[t] = 0.f;
            break;
        }

        int jx = jxy & 0xffff, jy = jxy >> 16;
        for (int i = tid; i < count; i += NT){
            int p = xyp[i];
            int dx = (p & 0xffff) - jx; dx = dx < 0 ? -dx : dx;
            int dy = (p >> 16)    - jy; dy = dy < 0 ? -dy : dy;
            if (dx <= 1 && dy <= 1) scp[i] = NEGV;
        }
        if (tid == 0){
            g_pick[bb*KPICKS + k]    = jxy;
            g_pick_sc[bb*KPICKS + k] = best;
        }
        __syncthreads();
    }
}

// ============================================================
// K5: exact reg head + box refinement for NMS picks only
// (<=128/batch). Conv3 acc recomputed in the SAME sequential
// (c,ky,q) order as the R5 engine -> identical reg values.
// grid (8, BB), 128 thr: 16 picks/block, 1 pick/thread.
// ============================================================
__global__ __launch_bounds__(128) void k5_finish(const float* __restrict__ b3,
                               const float* __restrict__ p3,
                               const float* __restrict__ w42, const float* __restrict__ b42,
                               float* __restrict__ out)
{
    __shared__ __align__(16) ull sw3[2304];   // [(c*9+k)*16 + q]
    __shared__ float sb[32], sp[32];
    __shared__ float sw42[128], sb42[4];
    int tid = threadIdx.x;
    {
        ulonglong2* d = reinterpret_cast<ulonglong2*>(sw3);
        const ulonglong2* s = reinterpret_cast<const ulonglong2*>(&g_stage[W3OFF]);
        for (int i = tid; i < 1152; i += 128) d[i] = s[i];
    }
    if (tid < 32){ sb[tid] = b3[tid]; sp[tid] = p3[tid]; }
    if (tid < 128) sw42[tid] = w42[tid];
    if (tid < 4)   sb42[tid] = b42[tid];
    __syncthreads();

    int bb = blockIdx.y;
    int pcnt = g_pcnt[bb];
    if (pcnt > KPICKS) pcnt = KPICKS;
    int k = blockIdx.x * 16 + tid;
    if (tid >= 16 || k >= pcnt) return;

    int jxy = g_pick[bb*KPICKS + k];
    int x = jxy & 0xffff;
    int y = jxy >> 16;

    ull acc[16];
#pragma unroll
    for (int q = 0; q < 16; q++) acc[q] = pack2(sb[2*q], sb[2*q+1]);

    for (int c = 0; c < 16; c++){
        const float* base = g_h2 + ((bb*16 + c)*PH + y)*SP + x;
#pragma unroll
        for (int ky = 0; ky < 3; ky++){
            float v0 = base[ky*SP + 0];
            float v1 = base[ky*SP + 1];
            float v2 = base[ky*SP + 2];
            ull d0 = pack2(v0,v0), d1 = pack2(v1,v1), d2 = pack2(v2,v2);
            const ull* wq = &sw3[(c*9 + ky*3)*16];
#pragma unroll
            for (int q = 0; q < 16; q++) fma2(acc[q], d0, wq[q]);
#pragma unroll
            for (int q = 0; q < 16; q++) fma2(acc[q], d1, wq[16+q]);
#pragma unroll
            for (int q = 0; q < 16; q++) fma2(acc[q], d2, wq[32+q]);
        }
    }

    float r0 = sb42[0], r1 = sb42[1], r2 = sb42[2], r3 = sb42[3];
#pragma unroll
    for (int q = 0; q < 16; q++){
        float hA, hB; unpack2(acc[q], hA, hB);
        float alo = sp[2*q], ahi = sp[2*q+1];
        hA = hA > 0.f ? hA : alo*hA;
        hB = hB > 0.f ? hB : ahi*hB;
        float q00 = sw42[2*q],    q01 = sw42[2*q+1];
        float q10 = sw42[32+2*q], q11 = sw42[32+2*q+1];
        float q20 = sw42[64+2*q], q21 = sw42[64+2*q+1];
        float q30 = sw42[96+2*q], q31 = sw42[96+2*q+1];
        r0 = fmaf(hA, q00, fmaf(hB, q01, r0));
        r1 = fmaf(hA, q10, fmaf(hB, q11, r1));
        r2 = fmaf(hA, q20, fmaf(hB, q21, r2));
        r3 = fmaf(hA, q30, fmaf(hB, q31, r3));
    }

    float x1 = 2.f*x + 1.f,  y1 = 2.f*y + 1.f;
    float x2 = 2.f*x + 12.f, y2 = 2.f*y + 12.f;
    float q1 = fmaf(r0, 11.f, x1);
    float q2 = fmaf(r1, 11.f, y1);
    float q3 = fmaf(r2, 11.f, x2);
    float q4 = fmaf(r3, 11.f, y2);
    float rw = q3 - q1, rh = q4 - q2;
    float l = fmaxf(rw, rh);
    float nx1 = q1 + rw*0.5f - l*0.5f;
    float ny1 = q2 + rh*0.5f - l*0.5f;
    float* o = out + ((size_t)bb*KPICKS + k)*5;
    o[0] = nx1; o[1] = ny1; o[2] = nx1 + l; o[3] = ny1 + l;
    o[4] = g_pick_sc[bb*KPICKS + k];
}

// ============================================================
extern "C" void kernel_launch(void* const* d_in, const int* in_sizes, int n_in,
                              void* d_out, int out_size)
{
    const float* im   = (const float*)d_in[0];
    const float* c1w  = (const float*)d_in[1];
    const float* c1b  = (const float*)d_in[2];
    const float* p1   = (const float*)d_in[3];
    const float* c2w  = (const float*)d_in[4];
    const float* c2b  = (const float*)d_in[5];
    const float* p2   = (const float*)d_in[6];
    const float* c3w  = (const float*)d_in[7];
    const float* c3b  = (const float*)d_in[8];
    const float* p3   = (const float*)d_in[9];
    const float* c41w = (const float*)d_in[10];
    const float* c41b = (const float*)d_in[11];
    const float* c42w = (const float*)d_in[12];
    const float* c42b = (const float*)d_in[13];
    float* out = (float*)d_out;

    // stage packed weights; copy to constant banks (async D2D, capturable)
    k0_pack<<<1, 256>>>(c1w, c2w, c3w);
    void* stage_ptr = nullptr;
    cudaGetSymbolAddress(&stage_ptr, g_stage);
    const char* sp8 = (const char*)stage_ptr;
    cudaMemcpyToSymbolAsync(c_w1, sp8 + (size_t)W1OFF*8, (size_t)W1N*8, 0,
                            cudaMemcpyDeviceToDevice, 0);
    cudaMemcpyToSymbolAsync(c_w2, sp8 + (size_t)W2OFF*8, (size_t)W2N*8, 0,
                            cudaMemcpyDeviceToDevice, 0);
    cudaMemcpyToSymbolAsync(c_w3, sp8 + (size_t)W3OFF*8, (size_t)W3N*8, 0,
                            cudaMemcpyDeviceToDevice, 0);

    dim3 blk1(32, 8, 1);
    dim3 g1(8, 24, BB);

    dim3 blk2(32, 2, 1);
    dim3 g2(2, 96, BB);   // 96*2 rows cover 189 (+pad, harmless as before)
    dim3 g3(2, 94, BB);   // 94*2 rows cover 187 (+1 pad row, discarded)

    k1_conv1_pool<<<g1, blk1>>>(im, c1b, p1);
    k2_conv2<<<g2, blk2>>>(c2b, p2);
    k3_conv3_heads<<<g3, blk2>>>(c3b, p3, c41w, c41b);
    k4_nms<<<BB, 256>>>(out);
    k5_finish<<<dim3(8, BB), 128>>>(c3b, p3, c42w, c42b, out);
}

// round 14
// speedup vs baseline: 1.0269x; 1.0269x over previous
#include <cuda_runtime.h>
#include <math.h>

typedef unsigned long long ull;

// ---- problem constants ----
#define BB  16
#define HH  384
#define WW  512
#define HPP 191
#define WPP 255
#define H2D 189
#define W2D 253
#define H3D 187
#define W3D 251
#define NPIX (H3D*W3D)   // 46937
#define NEGV (-1e30f)
#define THRESH_V 0.6f
#define KPICKS 128
#define CAP 5600
#define SP  260          // padded row stride (mult of 4)
#define PH  196          // padded plane height

// staging layout offsets (in ull) — ALL EVEN for aligned ulonglong2 loads
#define W1OFF 0
#define W1N   135
#define W2OFF 136
#define W2N   720
#define W3OFF 856
#define W3N   2304
#define WTOT  3160

// ---- scratch (zero-initialized device globals; padding deterministic) ----
__device__ __align__(16) float  g_pool[BB*10*PH*SP];
__device__ __align__(16) float  g_h2[BB*16*PH*SP];
__device__ __align__(16) ull    g_stage[WTOT];
__device__ int    g_cnt[BB];
__device__ int    g_cand[BB*NPIX];      // packed (y<<16)|x
__device__ float  g_cand_sc[BB*NPIX];

// ---- all packed oc-pair weights in ONE constant bank (one memcpy) ----
__constant__ ull c_wall[WTOT];

// ---- f32x2 helpers ----
__device__ __forceinline__ ull pack2(float lo, float hi){
    ull r; asm("mov.b64 %0, {%1, %2};" : "=l"(r) : "f"(lo), "f"(hi)); return r;
}
__device__ __forceinline__ void unpack2(ull v, float &lo, float &hi){
    asm("mov.b64 {%0, %1}, %2;" : "=f"(lo), "=f"(hi) : "l"(v));
}
__device__ __forceinline__ void fma2(ull &d, ull a, ull b){
    asm("fma.rn.f32x2 %0, %1, %2, %0;" : "+l"(d) : "l"(a), "l"(b));
}

// ============================================================
// K0: pack weights into oc-pair layout + zero counters
// ============================================================
__global__ void k0_pack(const float* __restrict__ w1,
                        const float* __restrict__ w2,
                        const float* __restrict__ w3)
{
    int tid = threadIdx.x;
    if (tid < BB) g_cnt[tid] = 0;
    for (int i = tid; i < W1N; i += 256){
        int ck = i / 5, q = i % 5;
        g_stage[W1OFF + i] = pack2(w1[(2*q)*27 + ck], w1[(2*q+1)*27 + ck]);
    }
    for (int i = tid; i < W2N; i += 256){
        int ck = i >> 3, q = i & 7;
        g_stage[W2OFF + i] = pack2(w2[(2*q)*90 + ck], w2[(2*q+1)*90 + ck]);
    }
    for (int i = tid; i < W3N; i += 256){
        int ck = i >> 4, q = i & 15;
        g_stage[W3OFF + i] = pack2(w3[(2*q)*144 + ck], w3[(2*q+1)*144 + ck]);
    }
}

// ============================================================
// K1: normalize + conv1(3x3,3->10) + PReLU + maxpool2x2  [R5/R12]
// ============================================================
__global__ __launch_bounds__(256) void k1_conv1_pool(const float* __restrict__ im,
                              const float* __restrict__ b,
                              const float* __restrict__ p)
{
    __shared__ float sb[10], sp[10];
    int tid = threadIdx.y * 32 + threadIdx.x;
    if (tid < 10){ sb[tid] = b[tid]; sp[tid] = p[tid]; }
    __syncthreads();

    int ox = blockIdx.x * 32 + threadIdx.x;
    int oy = blockIdx.y * 8  + threadIdx.y;
    int bb = blockIdx.z;
    if (ox >= WPP || oy >= HPP) return;

    ull acc[4][5];
#pragma unroll
    for (int q = 0; q < 5; q++){
        ull bi = pack2(sb[2*q], sb[2*q+1]);
        acc[0][q] = bi; acc[1][q] = bi; acc[2][q] = bi; acc[3][q] = bi;
    }

#pragma unroll
    for (int c = 0; c < 3; c++){
        const float* base = im + ((bb*3 + c)*HH + 2*oy)*WW + 2*ox;
        ull du[4][4];
#pragma unroll
        for (int r = 0; r < 4; r++){
            float2 u01 = *reinterpret_cast<const float2*>(base + r*WW);
            float2 u23 = *reinterpret_cast<const float2*>(base + r*WW + 2);
            float v0 = (u01.x - 127.5f)*0.0078125f;
            float v1 = (u01.y - 127.5f)*0.0078125f;
            float v2 = (u23.x - 127.5f)*0.0078125f;
            float v3 = (u23.y - 127.5f)*0.0078125f;
            du[r][0] = pack2(v0,v0); du[r][1] = pack2(v1,v1);
            du[r][2] = pack2(v2,v2); du[r][3] = pack2(v3,v3);
        }
#pragma unroll
        for (int ky = 0; ky < 3; ky++)
#pragma unroll
        for (int kx = 0; kx < 3; kx++){
            const ull* wq = &c_wall[W1OFF + (c*9 + ky*3 + kx)*5];
#pragma unroll
            for (int q = 0; q < 5; q++){
                ull wv = wq[q];
                fma2(acc[0][q], du[ky  ][kx  ], wv);
                fma2(acc[1][q], du[ky  ][kx+1], wv);
                fma2(acc[2][q], du[ky+1][kx  ], wv);
                fma2(acc[3][q], du[ky+1][kx+1], wv);
            }
        }
    }
#pragma unroll
    for (int q = 0; q < 5; q++){
        float h[4][2];
#pragma unroll
        for (int pp = 0; pp < 4; pp++) unpack2(acc[pp][q], h[pp][0], h[pp][1]);
#pragma unroll
        for (int s = 0; s < 2; s++){
            int oc = 2*q + s;
            float al = sp[oc];
            float m = -INFINITY;
#pragma unroll
            for (int pp = 0; pp < 4; pp++){
                float v = h[pp][s];
                v = v > 0.f ? v : al*v;
                m = fmaxf(m, v);
            }
            g_pool[((bb*10 + oc)*PH + oy)*SP + ox] = m;
        }
    }
}

// ============================================================
// K2: conv2(3x3,10->16) + PReLU, 4 px/thread  [R12: (32,4)=128t]
// ============================================================
__global__ __launch_bounds__(128) void k2_conv2(const float* __restrict__ b,
                         const float* __restrict__ p)
{
    __shared__ float sb[16], sp[16];
    int tid = threadIdx.y * 32 + threadIdx.x;
    if (tid < 16){ sb[tid] = b[tid]; sp[tid] = p[tid]; }
    __syncthreads();

    int x0 = blockIdx.x * 128 + threadIdx.x * 4;  // <= 252; reads <= 257 < SP
    int oy = blockIdx.y * 4   + threadIdx.y;      // <= 191; reads rows <= 193 < PH
    int bb = blockIdx.z;

    ull acc[4][8];
#pragma unroll
    for (int q = 0; q < 8; q++){
        ull bi = pack2(sb[2*q], sb[2*q+1]);
        acc[0][q] = bi; acc[1][q] = bi; acc[2][q] = bi; acc[3][q] = bi;
    }

    for (int c = 0; c < 10; c++){
        const float* base = g_pool + ((bb*10 + c)*PH + oy)*SP + x0;
        ull du[3][6];
#pragma unroll
        for (int r = 0; r < 3; r++){
            float4 a4 = *reinterpret_cast<const float4*>(base + r*SP);
            float2 b2 = *reinterpret_cast<const float2*>(base + r*SP + 4);
            du[r][0] = pack2(a4.x,a4.x); du[r][1] = pack2(a4.y,a4.y);
            du[r][2] = pack2(a4.z,a4.z); du[r][3] = pack2(a4.w,a4.w);
            du[r][4] = pack2(b2.x,b2.x); du[r][5] = pack2(b2.y,b2.y);
        }
#pragma unroll
        for (int ky = 0; ky < 3; ky++)
#pragma unroll
        for (int kx = 0; kx < 3; kx++){
            const ull* wq = &c_wall[W2OFF + (c*9 + ky*3 + kx)*8];
#pragma unroll
            for (int q = 0; q < 8; q++){
                ull wv = wq[q];
#pragma unroll
                for (int pp = 0; pp < 4; pp++)
                    fma2(acc[pp][q], du[ky][kx+pp], wv);
            }
        }
    }
#pragma unroll
    for (int q = 0; q < 8; q++){
        float v[4][2];
#pragma unroll
        for (int pp = 0; pp < 4; pp++) unpack2(acc[pp][q], v[pp][0], v[pp][1]);
#pragma unroll
        for (int s = 0; s < 2; s++){
            int oc = 2*q + s;
            float al = sp[oc];
            float4 o;
            float t0 = v[0][s]; o.x = t0 > 0.f ? t0 : al*t0;
            float t1 = v[1][s]; o.y = t1 > 0.f ? t1 : al*t1;
            float t2 = v[2][s]; o.z = t2 > 0.f ? t2 : al*t2;
            float t3 = v[3][s]; o.w = t3 > 0.f ? t3 : al*t3;
            *reinterpret_cast<float4*>(&g_h2[((bb*16 + oc)*PH + oy)*SP + x0]) = o;
        }
    }
}

// ============================================================
// K3: conv3(3x3,16->32)+PReLU + score head ONLY + append.
// [R12: (32,4)=128t, 4 px/thread; reg head deferred to k4 epilogue]
// ============================================================
__global__ __launch_bounds__(128) void k3_conv3_heads(const float* __restrict__ b3,
                               const float* __restrict__ p3,
                               const float* __restrict__ w41, const float* __restrict__ b41)
{
    __shared__ float sb[32], sp[32];
    __shared__ float sw41[64], sb41[2];
    int tid = threadIdx.y * 32 + threadIdx.x;
    if (tid < 32){ sb[tid] = b3[tid]; sp[tid] = p3[tid]; }
    if (tid < 64)  sw41[tid] = w41[tid];
    if (tid < 2)   sb41[tid] = b41[tid];
    __syncthreads();

    int x0 = blockIdx.x * 128 + threadIdx.x * 4;  // <= 252; reads <= 257 < SP
    int oy = blockIdx.y * 4   + threadIdx.y;      // <= 187; reads rows <= 189 < PH
    int bb = blockIdx.z;

    ull acc[4][16];
#pragma unroll
    for (int q = 0; q < 16; q++){
        ull bi = pack2(sb[2*q], sb[2*q+1]);
        acc[0][q] = bi; acc[1][q] = bi; acc[2][q] = bi; acc[3][q] = bi;
    }

    for (int c = 0; c < 16; c++){
        const float* base = g_h2 + ((bb*16 + c)*PH + oy)*SP + x0;
        ull du[3][6];
#pragma unroll
        for (int r = 0; r < 3; r++){
            float4 a4 = *reinterpret_cast<const float4*>(base + r*SP);
            float2 b2 = *reinterpret_cast<const float2*>(base + r*SP + 4);
            du[r][0] = pack2(a4.x,a4.x); du[r][1] = pack2(a4.y,a4.y);
            du[r][2] = pack2(a4.z,a4.z); du[r][3] = pack2(a4.w,a4.w);
            du[r][4] = pack2(b2.x,b2.x); du[r][5] = pack2(b2.y,b2.y);
        }
#pragma unroll
        for (int ky = 0; ky < 3; ky++)
#pragma unroll
        for (int kx = 0; kx < 3; kx++){
            const ull* wq = &c_wall[W3OFF + (c*9 + ky*3 + kx)*16];
#pragma unroll
            for (int q = 0; q < 16; q++){
                ull wv = wq[q];
#pragma unroll
                for (int pp = 0; pp < 4; pp++)
                    fma2(acc[pp][q], du[ky][kx+pp], wv);
            }
        }
    }

    // score head only (l chains identical — r-FMAs were independent)
    float l0[4], l1[4];
#pragma unroll
    for (int pp = 0; pp < 4; pp++){ l0[pp] = sb41[0]; l1[pp] = sb41[1]; }
#pragma unroll
    for (int q = 0; q < 16; q++){
        float wA0 = sw41[2*q],    wA1 = sw41[2*q+1];
        float wB0 = sw41[32+2*q], wB1 = sw41[32+2*q+1];
        float alo = sp[2*q], ahi = sp[2*q+1];
#pragma unroll
        for (int pp = 0; pp < 4; pp++){
            float hA, hB; unpack2(acc[pp][q], hA, hB);
            hA = hA > 0.f ? hA : alo*hA;
            hB = hB > 0.f ? hB : ahi*hB;
            l0[pp] = fmaf(hA, wA0, fmaf(hB, wA1, l0[pp]));
            l1[pp] = fmaf(hA, wB0, fmaf(hB, wB1, l1[pp]));
        }
    }
    if (oy < H3D){
#pragma unroll
        for (int pp = 0; pp < 4; pp++){
            int x = x0 + pp;
            if (x >= W3D) continue;
            float prob = 1.f / (1.f + expf(l0[pp] - l1[pp]));
            if (prob >= THRESH_V){
                int pos = atomicAdd(&g_cnt[bb], 1);
                if (pos < NPIX){
                    g_cand[bb*NPIX + pos]    = (oy << 16) | x;
                    g_cand_sc[bb*NPIX + pos] = prob;
                }
            }
        }
    }
}

// ============================================================
// K4: per-batch iterative argmax NMS + fused pick finishing.
// After the pick loop, the candidate shared buffer (dead) is
// overlaid with conv3 weights; each pick's conv3+reg head is
// recomputed with the R5-identical sequential (c,ky,q) chain,
// then the output row is written. Tie-break (score desc, xy asc)
// == pixel-index order. IoU>0.5 <=> |dx|<=1 && |dy|<=1.
// ============================================================
__global__ __launch_bounds__(256) void k4_nms(const float* __restrict__ b3,
                                              const float* __restrict__ p3,
                                              const float* __restrict__ w42,
                                              const float* __restrict__ b42,
                                              float* __restrict__ out)
{
    const int NT = 256;
    int bb = blockIdx.x, tid = threadIdx.x;
    int lane = tid & 31, wrp = tid >> 5;

    __shared__ __align__(16) char s_buf[CAP*8];   // candidates, then weights
    __shared__ float w_s[8];
    __shared__ int   w_xy[8], w_i[8];
    __shared__ float sh_best;
    __shared__ int   sh_j, sh_xy;
    __shared__ int   s_pick[KPICKS];
    __shared__ float s_psc[KPICKS];
    __shared__ int   s_pcnt;
    __shared__ float sb[32], sp[32], sw42[128], sb42[4];

    float* s_sc = reinterpret_cast<float*>(s_buf);
    int*   s_xy = reinterpret_cast<int*>(s_buf + CAP*4);

    if (tid == 0) s_pcnt = KPICKS;

    int count = g_cnt[bb];
    if (count > NPIX) count = NPIX;
    bool insh = (count <= CAP);
    float* scp;
    const int* xyp;
    if (insh){
        for (int i = tid; i < count; i += NT){
            s_sc[i] = g_cand_sc[bb*NPIX + i];
            s_xy[i] = g_cand[bb*NPIX + i];
        }
        scp = s_sc; xyp = s_xy;
    } else {
        scp = g_cand_sc + bb*NPIX;
        xyp = g_cand + bb*NPIX;
    }
    __syncthreads();

    for (int k = 0; k < KPICKS; k++){
        float bs = -INFINITY; int bxy = 0x7fffffff; int bi = -1;
        for (int i = tid; i < count; i += NT){
            float v = scp[i]; int xy = xyp[i];
            if (v > bs || (v == bs && xy < bxy)){ bs = v; bxy = xy; bi = i; }
        }
#pragma unroll
        for (int off = 16; off > 0; off >>= 1){
            float vs  = __shfl_down_sync(0xffffffffu, bs,  off);
            int   vxy = __shfl_down_sync(0xffffffffu, bxy, off);
            int   vi  = __shfl_down_sync(0xffffffffu, bi,  off);
            if (vs > bs || (vs == bs && vxy < bxy)){ bs = vs; bxy = vxy; bi = vi; }
        }
        if (lane == 0){ w_s[wrp] = bs; w_xy[wrp] = bxy; w_i[wrp] = bi; }
        __syncthreads();
        if (tid == 0){
            float cs = w_s[0]; int cxy = w_xy[0], ci = w_i[0];
#pragma unroll
            for (int t = 1; t < 8; t++){
                if (w_s[t] > cs || (w_s[t] == cs && w_xy[t] < cxy)){
                    cs = w_s[t]; cxy = w_xy[t]; ci = w_i[t];
                }
            }
            sh_best = cs; sh_j = ci; sh_xy = cxy;
        }
        __syncthreads();
        float best = sh_best; int j = sh_j; int jxy = sh_xy;

        if (!(best > -0.5e30f) || j < 0){
            if (tid == 0) s_pcnt = k;
            // exhausted: remaining picks have ok=false -> zero rows
            int n0 = (KPICKS - k) * 5;
            float* o0 = out + ((size_t)bb*KPICKS + k)*5;
            for (int t = tid; t < n0; t += NT) o0[t] = 0.f;
            break;
        }

        int jx = jxy & 0xffff, jy = jxy >> 16;
        for (int i = tid; i < count; i += NT){
            int p = xyp[i];
            int dx = (p & 0xffff) - jx; dx = dx < 0 ? -dx : dx;
            int dy = (p >> 16)    - jy; dy = dy < 0 ? -dy : dy;
            if (dx <= 1 && dy <= 1) scp[i] = NEGV;
        }
        if (tid == 0){ s_pick[k] = jxy; s_psc[k] = best; }
        __syncthreads();
    }

    // ---- epilogue: finish the <=128 picks (candidate buffer is dead) ----
    __syncthreads();
    ull* sw3 = reinterpret_cast<ull*>(s_buf);     // 2304 ull = 18432 B <= 44800 B
    {
        ulonglong2* d = reinterpret_cast<ulonglong2*>(sw3);
        const ulonglong2* s = reinterpret_cast<const ulonglong2*>(&g_stage[W3OFF]);
        for (int i = tid; i < 1152; i += NT) d[i] = s[i];
    }
    if (tid < 32){ sb[tid] = b3[tid]; sp[tid] = p3[tid]; }
    if (tid < 128) sw42[tid] = w42[tid];
    if (tid < 4)   sb42[tid] = b42[tid];
    __syncthreads();

    int pcnt = s_pcnt;
    if (tid < pcnt){
        int jxy = s_pick[tid];
        int x = jxy & 0xffff;
        int y = jxy >> 16;

        ull acc[16];
#pragma unroll
        for (int q = 0; q < 16; q++) acc[q] = pack2(sb[2*q], sb[2*q+1]);

        for (int c = 0; c < 16; c++){
            const float* base = g_h2 + ((bb*16 + c)*PH + y)*SP + x;
#pragma unroll
            for (int ky = 0; ky < 3; ky++){
                float v0 = base[ky*SP + 0];
                float v1 = base[ky*SP + 1];
                float v2 = base[ky*SP + 2];
                ull d0 = pack2(v0,v0), d1 = pack2(v1,v1), d2 = pack2(v2,v2);
                const ull* wq = &sw3[(c*9 + ky*3)*16];
#pragma unroll
                for (int q = 0; q < 16; q++) fma2(acc[q], d0, wq[q]);
#pragma unroll
                for (int q = 0; q < 16; q++) fma2(acc[q], d1, wq[16+q]);
#pragma unroll
                for (int q = 0; q < 16; q++) fma2(acc[q], d2, wq[32+q]);
            }
        }

        float r0 = sb42[0], r1 = sb42[1], r2 = sb42[2], r3 = sb42[3];
#pragma unroll
        for (int q = 0; q < 16; q++){
            float hA, hB; unpack2(acc[q], hA, hB);
            float alo = sp[2*q], ahi = sp[2*q+1];
            hA = hA > 0.f ? hA : alo*hA;
            hB = hB > 0.f ? hB : ahi*hB;
            float q00 = sw42[2*q],    q01 = sw42[2*q+1];
            float q10 = sw42[32+2*q], q11 = sw42[32+2*q+1];
            float q20 = sw42[64+2*q], q21 = sw42[64+2*q+1];
            float q30 = sw42[96+2*q], q31 = sw42[96+2*q+1];
            r0 = fmaf(hA, q00, fmaf(hB, q01, r0));
            r1 = fmaf(hA, q10, fmaf(hB, q11, r1));
            r2 = fmaf(hA, q20, fmaf(hB, q21, r2));
            r3 = fmaf(hA, q30, fmaf(hB, q31, r3));
        }

        float x1 = 2.f*x + 1.f,  y1 = 2.f*y + 1.f;
        float x2 = 2.f*x + 12.f, y2 = 2.f*y + 12.f;
        float q1 = fmaf(r0, 11.f, x1);
        float q2 = fmaf(r1, 11.f, y1);
        float q3 = fmaf(r2, 11.f, x2);
        float q4 = fmaf(r3, 11.f, y2);
        float rw = q3 - q1, rh = q4 - q2;
        float l = fmaxf(rw, rh);
        float nx1 = q1 + rw*0.5f - l*0.5f;
        float ny1 = q2 + rh*0.5f - l*0.5f;
        float* o = out + ((size_t)bb*KPICKS + tid)*5;
        o[0] = nx1; o[1] = ny1; o[2] = nx1 + l; o[3] = ny1 + l;
        o[4] = s_psc[tid];
    }
}

// ============================================================
extern "C" void kernel_launch(void* const* d_in, const int* in_sizes, int n_in,
                              void* d_out, int out_size)
{
    const float* im   = (const float*)d_in[0];
    const float* c1w  = (const float*)d_in[1];
    const float* c1b  = (const float*)d_in[2];
    const float* p1   = (const float*)d_in[3];
    const float* c2w  = (const float*)d_in[4];
    const float* c2b  = (const float*)d_in[5];
    const float* p2   = (const float*)d_in[6];
    const float* c3w  = (const float*)d_in[7];
    const float* c3b  = (const float*)d_in[8];
    const float* p3   = (const float*)d_in[9];
    const float* c41w = (const float*)d_in[10];
    const float* c41b = (const float*)d_in[11];
    const float* c42w = (const float*)d_in[12];
    const float* c42b = (const float*)d_in[13];
    float* out = (float*)d_out;

    // stage packed weights; ONE copy into the single constant bank
    k0_pack<<<1, 256>>>(c1w, c2w, c3w);
    void* stage_ptr = nullptr;
    cudaGetSymbolAddress(&stage_ptr, g_stage);
    cudaMemcpyToSymbolAsync(c_wall, stage_ptr, (size_t)WTOT*8, 0,
                            cudaMemcpyDeviceToDevice, 0);

    dim3 blk1(32, 8, 1);
    dim3 g1(8, 24, BB);

    dim3 blk2(32, 4, 1);
    dim3 g2(2, 48, BB);   // 48*4 rows cover 189 (+pad)
    dim3 g3(2, 47, BB);   // 47*4 rows cover 187 (+1 pad row, discarded)

    k1_conv1_pool<<<g1, blk1>>>(im, c1b, p1);
    k2_conv2<<<g2, blk2>>>(c2b, p2);
    k3_conv3_heads<<<g3, blk2>>>(c3b, p3, c41w, c41b);
    k4_nms<<<BB, 256>>>(c3b, p3, c42w, c42b, out);
}